// round 1
// baseline (speedup 1.0000x reference)
#include <cuda_runtime.h>
#include <cuda_bf16.h>
#include <cstdint>

// ---------------------------------------------------------------------------
// GAT 4-layer network, N=50000 nodes, E=800000 edges (+ N self-loops).
// dims: 256 -> 32 -> 64 -> 128 -> 128 -> fc 40
// ---------------------------------------------------------------------------

#define NMAX 50000
#define EMAX 800000
#define CMAX 128

// -------------------- device scratch (allocation-free rule) ---------------
__device__ int      g_src[EMAX];
__device__ int      g_dst[EMAX];
__device__ float    g_e[EMAX + NMAX];
__device__ __align__(16) float g_h[(size_t)NMAX * CMAX];
__device__ __align__(16) float g_aggA[(size_t)NMAX * CMAX];
__device__ __align__(16) float g_aggB[(size_t)NMAX * CMAX];
__device__ float    g_es[NMAX];
__device__ float    g_ed[NMAX];
__device__ unsigned g_max[NMAX];
__device__ float    g_sum[NMAX];
__device__ int      g_is64;

// monotone float <-> unsigned mapping for atomicMax on floats
__device__ __forceinline__ unsigned fenc(float f) {
    unsigned u = __float_as_uint(f);
    return (u & 0x80000000u) ? ~u : (u | 0x80000000u);
}
__device__ __forceinline__ float fdec(unsigned k) {
    unsigned u = (k & 0x80000000u) ? (k ^ 0x80000000u) : ~k;
    return __uint_as_float(u);
}

// -------------------- edge dtype detection + normalization ----------------
__global__ void detect_kernel(const void* eptr) {
    if (threadIdx.x == 0 && blockIdx.x == 0) {
        const int* p = (const int*)eptr;
        int all0 = 1;
        for (int i = 1; i < 128; i += 2)
            if (p[i] != 0) all0 = 0;
        g_is64 = all0;   // int64 little-endian with values < 2^31 -> odd words 0
    }
}

__global__ void convert_kernel(const void* eptr, int E) {
    int i = blockIdx.x * blockDim.x + threadIdx.x;
    if (i >= E) return;
    if (g_is64) {
        const long long* p = (const long long*)eptr;
        g_src[i] = (int)p[i];
        g_dst[i] = (int)p[E + i];
    } else {
        const int* p = (const int*)eptr;
        g_src[i] = p[i];
        g_dst[i] = p[E + i];
    }
}

// -------------------- per-layer init: agg <- bias, max/sum reset ----------
__global__ void init_kernel(float* __restrict__ agg, const float* __restrict__ b,
                            int n, int cout) {
    int idx = blockIdx.x * blockDim.x + threadIdx.x;
    int total = n * cout;
    if (idx < total) agg[idx] = b[idx % cout];
    if (idx < n) { g_max[idx] = 0u; g_sum[idx] = 0.0f; }
}

// -------------------- GEMM: h = act(in) @ W  (W cached in smem) ----------
template <int CIN, int COUT, bool RELU>
__global__ void gemm_kernel(const float* __restrict__ in,
                            const float* __restrict__ W, int n) {
    constexpr int TX = COUT / 4;       // threads along column dim (float4 each)
    constexpr int TY = 256 / TX;       // rows per block
    extern __shared__ float4 Ws[];     // CIN * TX float4

    int tid = threadIdx.x;
    const float4* W4 = reinterpret_cast<const float4*>(W);
    for (int i = tid; i < CIN * TX; i += 256) Ws[i] = W4[i];
    __syncthreads();

    int tx = tid % TX;
    int ty = tid / TX;
    int row = blockIdx.x * TY + ty;
    if (row >= n) return;

    const float4* in4 = reinterpret_cast<const float4*>(in + (size_t)row * CIN);
    float4 acc = make_float4(0.f, 0.f, 0.f, 0.f);

#pragma unroll 4
    for (int k4 = 0; k4 < CIN / 4; k4++) {
        float4 xv = __ldg(&in4[k4]);
        if (RELU) {
            xv.x = fmaxf(xv.x, 0.f); xv.y = fmaxf(xv.y, 0.f);
            xv.z = fmaxf(xv.z, 0.f); xv.w = fmaxf(xv.w, 0.f);
        }
#pragma unroll
        for (int j = 0; j < 4; j++) {
            float xs = (j == 0) ? xv.x : (j == 1) ? xv.y : (j == 2) ? xv.z : xv.w;
            float4 w = Ws[(k4 * 4 + j) * TX + tx];
            acc.x = fmaf(xs, w.x, acc.x);
            acc.y = fmaf(xs, w.y, acc.y);
            acc.z = fmaf(xs, w.z, acc.z);
            acc.w = fmaf(xs, w.w, acc.w);
        }
    }
    reinterpret_cast<float4*>(g_h)[(size_t)row * TX + tx] = acc;
}

// -------------------- per-row attention dots: es = h.a_s, ed = h.a_d ------
__global__ void edot_kernel(const float* __restrict__ as_,
                            const float* __restrict__ ad_, int n, int cout) {
    int warp = (blockIdx.x * blockDim.x + threadIdx.x) / 32;
    int lane = threadIdx.x & 31;
    if (warp >= n) return;
    const float* hrow = g_h + (size_t)warp * cout;
    float s = 0.f, d = 0.f;
    for (int c = lane; c < cout; c += 32) {
        float v = hrow[c];
        s = fmaf(v, as_[c], s);
        d = fmaf(v, ad_[c], d);
    }
#pragma unroll
    for (int off = 16; off > 0; off >>= 1) {
        s += __shfl_down_sync(0xffffffffu, s, off);
        d += __shfl_down_sync(0xffffffffu, d, off);
    }
    if (lane == 0) { g_es[warp] = s; g_ed[warp] = d; }
}

// -------------------- edge pass A: e = lrelu(es[src]+ed[dst]); max --------
__global__ void edgeA_kernel(int E, int n) {
    int idx = blockIdx.x * blockDim.x + threadIdx.x;
    if (idx >= E + n) return;
    int s, d;
    if (idx < E) { s = g_src[idx]; d = g_dst[idx]; }
    else         { s = d = idx - E; }
    float e = g_es[s] + g_ed[d];
    e = (e > 0.f) ? e : 0.2f * e;
    g_e[idx] = e;
    atomicMax(&g_max[d], fenc(e));
}

// -------------------- edge pass B: ex = exp(e - m[dst]); sum --------------
__global__ void edgeB_kernel(int E, int n) {
    int idx = blockIdx.x * blockDim.x + threadIdx.x;
    if (idx >= E + n) return;
    int d = (idx < E) ? g_dst[idx] : idx - E;
    float m = fdec(g_max[d]);
    float ex = __expf(g_e[idx] - m);
    g_e[idx] = ex;
    atomicAdd(&g_sum[d], ex);
}

// -------------------- edge pass C: agg[dst] += alpha * h[src] -------------
template <int COUT>
__global__ void edgeC_kernel(float* __restrict__ agg, int E, int n) {
    constexpr int TXC = COUT / 4;
    int idx = blockIdx.x * blockDim.x + threadIdx.x;
    int total = (E + n) * TXC;
    if (idx >= total) return;
    int eid = idx / TXC;
    int c4  = idx % TXC;
    int s, d;
    if (eid < E) { s = g_src[eid]; d = g_dst[eid]; }
    else          { s = d = eid - E; }
    float alpha = g_e[eid] / g_sum[d];
    float4 hv = reinterpret_cast<const float4*>(g_h)[(size_t)s * TXC + c4];
    float* o = agg + (size_t)d * COUT + c4 * 4;
    atomicAdd(o + 0, alpha * hv.x);
    atomicAdd(o + 1, alpha * hv.y);
    atomicAdd(o + 2, alpha * hv.z);
    atomicAdd(o + 3, alpha * hv.w);
}

// -------------------- final FC: out = relu(agg4) @ fcW + fcb --------------
__global__ void fc_kernel(const float* __restrict__ in,
                          const float* __restrict__ fcW,
                          const float* __restrict__ fcb,
                          float* __restrict__ out, int n) {
    __shared__ float Ws[128 * 40];
    int tid = threadIdx.x;                 // blockDim = 320
    for (int i = tid; i < 128 * 40; i += 320) Ws[i] = fcW[i];
    __syncthreads();
    int tx = tid % 40;
    int ty = tid / 40;                     // 8 rows/block
    int row = blockIdx.x * 8 + ty;
    if (row >= n) return;
    const float* irow = in + (size_t)row * 128;
    float acc = 0.f;
#pragma unroll 8
    for (int k = 0; k < 128; k++) {
        float v = fmaxf(irow[k], 0.f);
        acc = fmaf(v, Ws[k * 40 + tx], acc);
    }
    out[(size_t)row * 40 + tx] = acc + fcb[tx];
}

// ---------------------------------------------------------------------------
// host driver
// ---------------------------------------------------------------------------
static inline int ceil_div(int a, int b) { return (a + b - 1) / b; }

template <int CIN, int COUT, bool RELU>
static void launch_gemm(const float* in, const float* W, int n) {
    constexpr int TX = COUT / 4;
    constexpr int TY = 256 / TX;
    size_t smem = (size_t)CIN * TX * sizeof(float4);
    if (smem > 48 * 1024) {
        cudaFuncSetAttribute((const void*)gemm_kernel<CIN, COUT, RELU>,
                             cudaFuncAttributeMaxDynamicSharedMemorySize,
                             (int)smem);
    }
    gemm_kernel<CIN, COUT, RELU><<<ceil_div(n, TY), 256, smem>>>(in, W, n);
}

template <int COUT>
static void run_edge_phase(float* agg, int E, int n) {
    int tot = E + n;
    edgeA_kernel<<<ceil_div(tot, 256), 256>>>(E, n);
    edgeB_kernel<<<ceil_div(tot, 256), 256>>>(E, n);
    int totc = tot * (COUT / 4);
    edgeC_kernel<COUT><<<ceil_div(totc, 256), 256>>>(agg, E, n);
}

extern "C" void kernel_launch(void* const* d_in, const int* in_sizes, int n_in,
                              void* d_out, int out_size) {
    const float* x  = (const float*)d_in[0];
    const void*  ei = d_in[1];
    const float* W1 = (const float*)d_in[2];
    const float* a1s = (const float*)d_in[3];
    const float* a1d = (const float*)d_in[4];
    const float* b1 = (const float*)d_in[5];
    const float* W2 = (const float*)d_in[6];
    const float* a2s = (const float*)d_in[7];
    const float* a2d = (const float*)d_in[8];
    const float* b2 = (const float*)d_in[9];
    const float* W3 = (const float*)d_in[10];
    const float* a3s = (const float*)d_in[11];
    const float* a3d = (const float*)d_in[12];
    const float* b3 = (const float*)d_in[13];
    const float* W4 = (const float*)d_in[14];
    const float* a4s = (const float*)d_in[15];
    const float* a4d = (const float*)d_in[16];
    const float* b4 = (const float*)d_in[17];
    const float* fcW = (const float*)d_in[18];
    const float* fcb = (const float*)d_in[19];

    const int n = in_sizes[0] / 256;
    const int E = in_sizes[1] / 2;

    float* aggA; cudaGetSymbolAddress((void**)&aggA, g_aggA);
    float* aggB; cudaGetSymbolAddress((void**)&aggB, g_aggB);

    // normalize edge index dtype into int32 scratch
    detect_kernel<<<1, 32>>>(ei);
    convert_kernel<<<ceil_div(E, 256), 256>>>(ei, E);

    // ---- layer 1: 256 -> 32 (input x, no relu on load) ----
    init_kernel<<<ceil_div(n * 32, 256), 256>>>(aggA, b1, n, 32);
    launch_gemm<256, 32, false>(x, W1, n);
    edot_kernel<<<ceil_div(n, 8), 256>>>(a1s, a1d, n, 32);
    run_edge_phase<32>(aggA, E, n);

    // ---- layer 2: 32 -> 64 (relu on load) ----
    init_kernel<<<ceil_div(n * 64, 256), 256>>>(aggB, b2, n, 64);
    launch_gemm<32, 64, true>(aggA, W2, n);
    edot_kernel<<<ceil_div(n, 8), 256>>>(a2s, a2d, n, 64);
    run_edge_phase<64>(aggB, E, n);

    // ---- layer 3: 64 -> 128 ----
    init_kernel<<<ceil_div(n * 128, 256), 256>>>(aggA, b3, n, 128);
    launch_gemm<64, 128, true>(aggB, W3, n);
    edot_kernel<<<ceil_div(n, 8), 256>>>(a3s, a3d, n, 128);
    run_edge_phase<128>(aggA, E, n);

    // ---- layer 4: 128 -> 128 ----
    init_kernel<<<ceil_div(n * 128, 256), 256>>>(aggB, b4, n, 128);
    launch_gemm<128, 128, true>(aggA, W4, n);
    edot_kernel<<<ceil_div(n, 8), 256>>>(a4s, a4d, n, 128);
    run_edge_phase<128>(aggB, E, n);

    // ---- final fc: relu(agg4) @ fcW + fcb ----
    fc_kernel<<<ceil_div(n, 8), 320>>>(aggB, fcW, fcb, (float*)d_out, n);
}

// round 2
// speedup vs baseline: 2.7920x; 2.7920x over previous
#include <cuda_runtime.h>
#include <cstdint>

// ---------------------------------------------------------------------------
// GAT 4-layer network, N=50000 nodes, E=800000 edges (+ N self-loops).
// dims: 256 -> 32 -> 64 -> 128 -> 128 -> fc 40
// R2: CSR-based atomic-free aggregation + 4x4 register-blocked GEMM.
// ---------------------------------------------------------------------------

#define NMAX 50000
#define EMAX 800000
#define CMAX 128
#define TOTE (EMAX + NMAX)

// -------------------- device scratch (allocation-free rule) ---------------
__device__ int      g_src[EMAX];
__device__ int      g_dst[EMAX];
__device__ int      g_cnt[NMAX];
__device__ int      g_rowptr[NMAX + 1];
__device__ int      g_cursor[NMAX];
__device__ int      g_csr_src[TOTE];
__device__ int      g_blocksum[512];
__device__ float    g_e[TOTE];
__device__ __align__(16) float g_h[(size_t)NMAX * CMAX];
__device__ __align__(16) float g_aggA[(size_t)NMAX * CMAX];
__device__ __align__(16) float g_aggB[(size_t)NMAX * CMAX];
__device__ float    g_es[NMAX];
__device__ float    g_ed[NMAX];
__device__ int      g_is64;

// -------------------- edge dtype detection + normalization ----------------
__global__ void detect_kernel(const void* eptr) {
    if (threadIdx.x == 0 && blockIdx.x == 0) {
        const int* p = (const int*)eptr;
        int all0 = 1;
        for (int i = 1; i < 128; i += 2)
            if (p[i] != 0) all0 = 0;
        g_is64 = all0;   // int64 little-endian with values < 2^31 -> odd words 0
    }
}

// also zeroes the CSR count array (n <= E always here)
__global__ void convert_kernel(const void* eptr, int E, int n) {
    int i = blockIdx.x * blockDim.x + threadIdx.x;
    if (i < n) g_cnt[i] = 0;
    if (i >= E) return;
    if (g_is64) {
        const long long* p = (const long long*)eptr;
        g_src[i] = (int)p[i];
        g_dst[i] = (int)p[E + i];
    } else {
        const int* p = (const int*)eptr;
        g_src[i] = p[i];
        g_dst[i] = p[E + i];
    }
}

// -------------------- CSR build: count / scan / scatter -------------------
__global__ void count_kernel(int E, int n) {
    int idx = blockIdx.x * blockDim.x + threadIdx.x;
    if (idx >= E + n) return;
    int d = (idx < E) ? g_dst[idx] : idx - E;
    atomicAdd(&g_cnt[d], 1);
}

__global__ void scan1_kernel(int n) {
    int tid = threadIdx.x;
    int idx = blockIdx.x * 256 + tid;
    int v = (idx < n) ? g_cnt[idx] : 0;
    int lane = tid & 31, w = tid >> 5;
#pragma unroll
    for (int o = 16; o; o >>= 1) v += __shfl_down_sync(0xffffffffu, v, o);
    __shared__ int ws[8];
    if (lane == 0) ws[w] = v;
    __syncthreads();
    if (tid == 0) {
        int s = 0;
#pragma unroll
        for (int i = 0; i < 8; i++) s += ws[i];
        g_blocksum[blockIdx.x] = s;
    }
}

__global__ void scan2_kernel(int nb) {
    if (threadIdx.x == 0) {
        int acc = 0;
        for (int i = 0; i < nb; i++) {
            int t = g_blocksum[i];
            g_blocksum[i] = acc;
            acc += t;
        }
    }
}

__global__ void scan3_kernel(int n) {
    int tid = threadIdx.x;
    int idx = blockIdx.x * 256 + tid;
    int v = (idx < n) ? g_cnt[idx] : 0;
    int lane = tid & 31, w = tid >> 5;
    unsigned full = 0xffffffffu;
    int x = v;
#pragma unroll
    for (int o = 1; o < 32; o <<= 1) {
        int y = __shfl_up_sync(full, x, o);
        if (lane >= o) x += y;
    }
    __shared__ int wsum[8];
    __shared__ int woff[8];
    if (lane == 31) wsum[w] = x;
    __syncthreads();
    if (tid < 8) {
        int s = wsum[tid];
#pragma unroll
        for (int o = 1; o < 8; o <<= 1) {
            int y = __shfl_up_sync(0xffu, s, o);
            if (tid >= o) s += y;
        }
        woff[tid] = s - wsum[tid];
    }
    __syncthreads();
    int excl = x - v + woff[w] + g_blocksum[blockIdx.x];
    if (idx < n) {
        g_rowptr[idx] = excl;
        g_cursor[idx] = excl;
        if (idx == n - 1) g_rowptr[n] = excl + v;
    }
}

__global__ void scatter_kernel(int E, int n) {
    int idx = blockIdx.x * blockDim.x + threadIdx.x;
    if (idx >= E + n) return;
    int s, d;
    if (idx < E) { s = g_src[idx]; d = g_dst[idx]; }
    else         { s = d = idx - E; }
    int pos = atomicAdd(&g_cursor[d], 1);
    g_csr_src[pos] = s;
}

// -------------------- GEMM: h = act(in) @ W  (4x4 register blocked) -------
template <int CIN, int COUT, bool RELU>
__global__ void gemm_kernel(const float* __restrict__ in,
                            const float* __restrict__ W, int n) {
    constexpr int TX = COUT / 4;       // threads along column dim (float4 each)
    constexpr int TY = 256 / TX;       // thread-rows per block
    constexpr int R  = 4;              // rows per thread
    extern __shared__ float4 Ws[];     // CIN * TX float4

    int tid = threadIdx.x;
    const float4* W4 = reinterpret_cast<const float4*>(W);
    for (int i = tid; i < CIN * TX; i += 256) Ws[i] = W4[i];
    __syncthreads();

    int tx = tid % TX;
    int ty = tid / TX;
    int row0 = (blockIdx.x * TY + ty) * R;

    const float4* inp[R];
#pragma unroll
    for (int r = 0; r < R; r++) {
        int rc = min(row0 + r, n - 1);
        inp[r] = reinterpret_cast<const float4*>(in + (size_t)rc * CIN);
    }

    float4 acc[R];
#pragma unroll
    for (int r = 0; r < R; r++) acc[r] = make_float4(0.f, 0.f, 0.f, 0.f);

#pragma unroll 2
    for (int k4 = 0; k4 < CIN / 4; k4++) {
        float4 xv[R];
#pragma unroll
        for (int r = 0; r < R; r++) {
            xv[r] = __ldg(&inp[r][k4]);
            if (RELU) {
                xv[r].x = fmaxf(xv[r].x, 0.f); xv[r].y = fmaxf(xv[r].y, 0.f);
                xv[r].z = fmaxf(xv[r].z, 0.f); xv[r].w = fmaxf(xv[r].w, 0.f);
            }
        }
#pragma unroll
        for (int j = 0; j < 4; j++) {
            float4 w = Ws[(k4 * 4 + j) * TX + tx];
#pragma unroll
            for (int r = 0; r < R; r++) {
                float xs = (j == 0) ? xv[r].x : (j == 1) ? xv[r].y
                         : (j == 2) ? xv[r].z : xv[r].w;
                acc[r].x = fmaf(xs, w.x, acc[r].x);
                acc[r].y = fmaf(xs, w.y, acc[r].y);
                acc[r].z = fmaf(xs, w.z, acc[r].z);
                acc[r].w = fmaf(xs, w.w, acc[r].w);
            }
        }
    }

    float4* out4 = reinterpret_cast<float4*>(g_h);
#pragma unroll
    for (int r = 0; r < R; r++) {
        int row = row0 + r;
        if (row < n) out4[(size_t)row * TX + tx] = acc[r];
    }
}

// -------------------- per-row attention dots: es = h.a_s, ed = h.a_d ------
__global__ void edot_kernel(const float* __restrict__ as_,
                            const float* __restrict__ ad_, int n, int cout) {
    int warp = (blockIdx.x * blockDim.x + threadIdx.x) / 32;
    int lane = threadIdx.x & 31;
    if (warp >= n) return;
    const float* hrow = g_h + (size_t)warp * cout;
    float s = 0.f, d = 0.f;
    for (int c = lane; c < cout; c += 32) {
        float v = hrow[c];
        s = fmaf(v, as_[c], s);
        d = fmaf(v, ad_[c], d);
    }
#pragma unroll
    for (int off = 16; off > 0; off >>= 1) {
        s += __shfl_down_sync(0xffffffffu, s, off);
        d += __shfl_down_sync(0xffffffffu, d, off);
    }
    if (lane == 0) { g_es[warp] = s; g_ed[warp] = d; }
}

// -------------------- fused edge phase: softmax + aggregate (warp/dst) ----
template <int COUT>
__global__ void gat_edge_kernel(const float* __restrict__ b,
                                float* __restrict__ agg, int n) {
    constexpr int RC = COUT / 32;
    int lane = threadIdx.x & 31;
    int d = blockIdx.x * 8 + (threadIdx.x >> 5);
    if (d >= n) return;

    int r0 = g_rowptr[d];
    int r1 = g_rowptr[d + 1];
    float edd = g_ed[d];

    // phase 1: e = leaky_relu(es[src] + ed[dst]); warp max
    float mx = -3.4e38f;
    for (int i = r0 + lane; i < r1; i += 32) {
        float e = g_es[g_csr_src[i]] + edd;
        e = (e > 0.f) ? e : 0.2f * e;
        g_e[i] = e;
        mx = fmaxf(mx, e);
    }
#pragma unroll
    for (int o = 16; o; o >>= 1) mx = fmaxf(mx, __shfl_xor_sync(0xffffffffu, mx, o));

    // phase 2: exp + warp sum
    float sum = 0.f;
    for (int i = r0 + lane; i < r1; i += 32) {
        float ex = __expf(g_e[i] - mx);
        g_e[i] = ex;
        sum += ex;
    }
#pragma unroll
    for (int o = 16; o; o >>= 1) sum += __shfl_xor_sync(0xffffffffu, sum, o);
    float inv = 1.0f / sum;
    __syncwarp();

    // phase 3: agg[d] = bias + sum alpha * h[src]   (lane owns columns)
    float acc[RC];
#pragma unroll
    for (int r = 0; r < RC; r++) acc[r] = __ldg(&b[lane + 32 * r]);

    for (int i = r0; i < r1; i++) {
        int s = g_csr_src[i];
        float alpha = g_e[i] * inv;
        const float* hp = g_h + (size_t)s * COUT + lane;
#pragma unroll
        for (int r = 0; r < RC; r++)
            acc[r] = fmaf(alpha, hp[32 * r], acc[r]);
    }

    float* op = agg + (size_t)d * COUT + lane;
#pragma unroll
    for (int r = 0; r < RC; r++) op[32 * r] = acc[r];
}

// -------------------- final FC: out = relu(agg4) @ fcW + fcb --------------
__global__ void fc_kernel(const float* __restrict__ in,
                          const float* __restrict__ fcW,
                          const float* __restrict__ fcb,
                          float* __restrict__ out, int n) {
    __shared__ float Ws[128 * 40];
    int tid = threadIdx.x;                 // blockDim = 320
    for (int i = tid; i < 128 * 40; i += 320) Ws[i] = fcW[i];
    __syncthreads();
    int tx = tid % 40;
    int ty = tid / 40;                     // 8 rows/block
    int row = blockIdx.x * 8 + ty;
    if (row >= n) return;
    const float* irow = in + (size_t)row * 128;
    float acc = 0.f;
#pragma unroll 8
    for (int k = 0; k < 128; k++) {
        float v = fmaxf(irow[k], 0.f);
        acc = fmaf(v, Ws[k * 40 + tx], acc);
    }
    out[(size_t)row * 40 + tx] = acc + fcb[tx];
}

// ---------------------------------------------------------------------------
// host driver
// ---------------------------------------------------------------------------
static inline int ceil_div(int a, int b) { return (a + b - 1) / b; }

template <int CIN, int COUT, bool RELU>
static void launch_gemm(const float* in, const float* W, int n) {
    constexpr int TX = COUT / 4;
    constexpr int TY = 256 / TX;
    constexpr int R  = 4;
    size_t smem = (size_t)CIN * TX * sizeof(float4);
    if (smem > 48 * 1024) {
        cudaFuncSetAttribute((const void*)gemm_kernel<CIN, COUT, RELU>,
                             cudaFuncAttributeMaxDynamicSharedMemorySize,
                             (int)smem);
    }
    gemm_kernel<CIN, COUT, RELU><<<ceil_div(n, TY * R), 256, smem>>>(in, W, n);
}

extern "C" void kernel_launch(void* const* d_in, const int* in_sizes, int n_in,
                              void* d_out, int out_size) {
    const float* x   = (const float*)d_in[0];
    const void*  ei  = d_in[1];
    const float* W1  = (const float*)d_in[2];
    const float* a1s = (const float*)d_in[3];
    const float* a1d = (const float*)d_in[4];
    const float* b1  = (const float*)d_in[5];
    const float* W2  = (const float*)d_in[6];
    const float* a2s = (const float*)d_in[7];
    const float* a2d = (const float*)d_in[8];
    const float* b2  = (const float*)d_in[9];
    const float* W3  = (const float*)d_in[10];
    const float* a3s = (const float*)d_in[11];
    const float* a3d = (const float*)d_in[12];
    const float* b3  = (const float*)d_in[13];
    const float* W4  = (const float*)d_in[14];
    const float* a4s = (const float*)d_in[15];
    const float* a4d = (const float*)d_in[16];
    const float* b4  = (const float*)d_in[17];
    const float* fcW = (const float*)d_in[18];
    const float* fcb = (const float*)d_in[19];

    const int n = in_sizes[0] / 256;
    const int E = in_sizes[1] / 2;
    const int tot = E + n;
    const int nb = ceil_div(n, 256);

    float* aggA; cudaGetSymbolAddress((void**)&aggA, g_aggA);
    float* aggB; cudaGetSymbolAddress((void**)&aggB, g_aggB);

    // ---- edge index normalization + CSR build (once per launch) ----
    detect_kernel<<<1, 32>>>(ei);
    convert_kernel<<<ceil_div(E, 256), 256>>>(ei, E, n);
    count_kernel<<<ceil_div(tot, 256), 256>>>(E, n);
    scan1_kernel<<<nb, 256>>>(n);
    scan2_kernel<<<1, 32>>>(nb);
    scan3_kernel<<<nb, 256>>>(n);
    scatter_kernel<<<ceil_div(tot, 256), 256>>>(E, n);

    // ---- layer 1: 256 -> 32 ----
    launch_gemm<256, 32, false>(x, W1, n);
    edot_kernel<<<ceil_div(n, 8), 256>>>(a1s, a1d, n, 32);
    gat_edge_kernel<32><<<ceil_div(n, 8), 256>>>(b1, aggA, n);

    // ---- layer 2: 32 -> 64 ----
    launch_gemm<32, 64, true>(aggA, W2, n);
    edot_kernel<<<ceil_div(n, 8), 256>>>(a2s, a2d, n, 64);
    gat_edge_kernel<64><<<ceil_div(n, 8), 256>>>(b2, aggB, n);

    // ---- layer 3: 64 -> 128 ----
    launch_gemm<64, 128, true>(aggB, W3, n);
    edot_kernel<<<ceil_div(n, 8), 256>>>(a3s, a3d, n, 128);
    gat_edge_kernel<128><<<ceil_div(n, 8), 256>>>(b3, aggA, n);

    // ---- layer 4: 128 -> 128 ----
    launch_gemm<128, 128, true>(aggA, W4, n);
    edot_kernel<<<ceil_div(n, 8), 256>>>(a4s, a4d, n, 128);
    gat_edge_kernel<128><<<ceil_div(n, 8), 256>>>(b4, aggB, n);

    // ---- final fc: relu(agg4) @ fcW + fcb ----
    fc_kernel<<<ceil_div(n, 8), 320>>>(aggB, fcW, fcb, (float*)d_out, n);
}